// round 16
// baseline (speedup 1.0000x reference)
#include <cuda_runtime.h>
#include <cuda_fp16.h>
#include <stdint.h>
#include <math.h>

// Problem shape (fixed): B=4, S=2048, D=1024
#define BATCH 4
#define SEQ   2048
#define DIM   1024
#define ROWS  (BATCH*SEQ)          // 8192
#define QK_SCALE 0.0220970869f     // 1/sqrt(2048)

// fp16 GEMM tiling (R13 validated): CTA 128x128, BK=64; 8 warps (4x2) -> 32x64
#define BM 128
#define BN 128
#define BK 64
#define STG 32768                  // A 16K | B 16K (fp16)
#define SMEMSZ (3*STG)             // 96KB, 3-stage ring

// ---------------- scratch (device globals; no allocation allowed) -----------
__device__ __half g_ln1 [ROWS*DIM];
__device__ __half g_qk  [ROWS*2*DIM];             // fused Q|K [ROWS, 2048]
__device__ __half g_vt  [ROWS*DIM];               // V^T per batch [D, S]
__device__ __half g_ctx [ROWS*DIM];
__device__ float  g_h   [ROWS*DIM];
__device__ __half g_ln2 [ROWS*DIM];
__device__ __half g_m1  [ROWS*DIM];
__device__ __half g_sc  [(size_t)BATCH*SEQ*SEQ];  // raw scores fp16 (32MB)
__device__ __half g_sp  [(size_t)BATCH*SEQ*SEQ];  // fp16 probs (32MB)
__device__ __half g_wt  [6*DIM*DIM];              // transposed weights fp16
__device__ float  g_bqk [2*DIM];                  // concat bias bq|bk

// ======================= helpers =============================================
__device__ __forceinline__ uint32_t smem_u32(const void* p) {
    uint32_t a;
    asm("{ .reg .u64 t; cvta.to.shared.u64 t, %1; cvt.u32.u64 %0, t; }"
        : "=r"(a) : "l"(p));
    return a;
}
__device__ __forceinline__ void cp16(uint32_t dst, const void* src) {
    asm volatile("cp.async.cg.shared.global [%0], [%1], 16;"
                 :: "r"(dst), "l"(src) : "memory");
}
__device__ __forceinline__ uint32_t sw128o(uint32_t o) {
    return o ^ ((o >> 3) & 0x70);
}
__device__ __forceinline__ void ldsm_x4(uint32_t* r, uint32_t addr) {
    asm volatile("ldmatrix.sync.aligned.m8n8.x4.shared.b16 {%0,%1,%2,%3}, [%4];"
                 : "=r"(r[0]), "=r"(r[1]), "=r"(r[2]), "=r"(r[3]) : "r"(addr));
}
__device__ __forceinline__ void mma_fp16(float* c, const uint32_t* a,
                                         uint32_t b0, uint32_t b1) {
    asm volatile("mma.sync.aligned.m16n8k16.row.col.f32.f16.f16.f32 "
                 "{%0,%1,%2,%3}, {%4,%5,%6,%7}, {%8,%9}, {%0,%1,%2,%3};"
                 : "+f"(c[0]), "+f"(c[1]), "+f"(c[2]), "+f"(c[3])
                 : "r"(a[0]), "r"(a[1]), "r"(a[2]), "r"(a[3]), "r"(b0), "r"(b1));
}

// ============ fp16 HMMA GEMM (R13 core): C[M,N] = A[M,K] @ B[N,K]^T ==========
// fp32 accumulate; bias/res/relu on fp32 accumulators.
// MODE: 0=dense, 1=QK (scale, causal block-skip), 2=AV (causal K-limit,
//       heavy-tiles-first)
// OUTP: 0 -> fp32 C (+res), 1 -> fp16 C, 2 -> fp16 transposed V^T
template<int MODE, bool RELU, int OUTP>
__global__ void __launch_bounds__(256, 2)
fp16_gemm(const __half* __restrict__ A, const __half* __restrict__ B,
          const float* __restrict__ bias, const float* __restrict__ res,
          void* __restrict__ Cv, int K, int ldA, int ldB, int ldC,
          size_t sA, size_t sB, size_t sC)
{
    int by = (MODE == 2) ? (gridDim.y - 1 - blockIdx.y) : blockIdx.y;
    int cRow = by * BM;
    int cCol = blockIdx.x * BN;
    if (MODE == 1 && cCol > cRow + BM - 1) return;   // fully above diagonal

    A += blockIdx.z * sA;
    B += blockIdx.z * sB;
    float*  Cf = (float*)Cv + (OUTP == 0 ? blockIdx.z * sC : 0);
    __half* Ch = (__half*)Cv + (OUTP == 1 ? blockIdx.z * sC : 0);
    if (OUTP == 0 && res) res += blockIdx.z * sC;

    int nc = (MODE == 2) ? (cRow + BM) / BK : K / BK;

    extern __shared__ __align__(1024) char smem[];
    uint32_t base = smem_u32(smem);
    int tid = threadIdx.x, lane = tid & 31, wid = tid >> 5;
    int wm = wid >> 1, wn = wid & 1;      // 4x2 warp grid, warp tile 32x64

    auto stage = [&](int c) {
        int kt = c * BK;
        uint32_t sb = base + (c % 3) * STG;
#pragma unroll
        for (int i = 0; i < 4; i++) {                 // A: 1024 granules of 16B
            int g = tid + i * 256;
            int row = g >> 3, ch = g & 7;
            cp16(sb + sw128o((uint32_t)(row * 128 + ch * 16)),
                 A + (size_t)(cRow + row) * ldA + kt + ch * 8);
        }
#pragma unroll
        for (int i = 0; i < 4; i++) {                 // B: 1024 granules
            int g = tid + i * 256;
            int row = g >> 3, ch = g & 7;
            cp16(sb + 16384 + sw128o((uint32_t)(row * 128 + ch * 16)),
                 B + (size_t)(cCol + row) * ldB + kt + ch * 8);
        }
        asm volatile("cp.async.commit_group;" ::: "memory");
    };

    float acc[2][8][4];
#pragma unroll
    for (int mi = 0; mi < 2; mi++)
#pragma unroll
        for (int ni = 0; ni < 8; ni++)
#pragma unroll
            for (int j = 0; j < 4; j++) acc[mi][ni][j] = 0.f;

    // fp16 m16n8k16 fragment offsets (validated mapping, non-trans B)
    int a_r  = lane & 15;
    int a_kb = (lane >> 4) << 4;
    int b_n  = (lane & 7) + ((lane >> 4) << 3);
    int b_kb = ((lane >> 3) & 1) << 4;

    stage(0);
    if (nc > 1) stage(1);
    for (int c = 0; c < nc; c++) {
        if (c + 1 < nc) {
            asm volatile("cp.async.wait_group 1;" ::: "memory");
        } else {
            asm volatile("cp.async.wait_group 0;" ::: "memory");
        }
        __syncthreads();
        // stage slot (c+2)%3 == (c-1)%3: its only reader (compute c-1) is
        // done by the barrier above — no trailing sync needed.
        if (c + 2 < nc) stage(c + 2);

        uint32_t sb = base + (c % 3) * STG;
        uint32_t aB = sb, bB = sb + 16384;
#pragma unroll
        for (int ks = 0; ks < 4; ks++) {              // 4 k16 steps
            uint32_t a[2][4];
#pragma unroll
            for (int mi = 0; mi < 2; mi++) {
                int r = wm * 32 + mi * 16 + a_r;
                ldsm_x4(a[mi], aB + sw128o((uint32_t)(r * 128 + ks * 32 + a_kb)));
            }
#pragma unroll
            for (int pp = 0; pp < 4; pp++) {          // b loaded+consumed: 4 live
                uint32_t b[4];
                int n = wn * 64 + pp * 16 + b_n;
                ldsm_x4(b, bB + sw128o((uint32_t)(n * 128 + ks * 32 + b_kb)));
#pragma unroll
                for (int mi = 0; mi < 2; mi++) {
                    mma_fp16(acc[mi][pp * 2],     a[mi], b[0], b[1]);
                    mma_fp16(acc[mi][pp * 2 + 1], a[mi], b[2], b[3]);
                }
            }
        }
    }

    // ---- epilogue ----
    if (OUTP == 2) {
        __syncthreads();   // all warps done with mainloop smem before reuse
        // transposed fp16 store: acc -> smem [col][row] -> coalesced V^T write
        float* ts = (float*)smem;                     // 128 x 132 floats (67.6KB)
#pragma unroll
        for (int mi = 0; mi < 2; mi++)
#pragma unroll
            for (int ni = 0; ni < 8; ni++) {
                int rL = wm * 32 + mi * 16 + (lane >> 2);
                int cL = wn * 64 + ni * 8 + (lane & 3) * 2;
#pragma unroll
                for (int hh = 0; hh < 2; hh++) {
                    float v0 = acc[mi][ni][hh * 2];
                    float v1 = acc[mi][ni][hh * 2 + 1];
                    if (bias) { v0 += bias[cCol + cL]; v1 += bias[cCol + cL + 1]; }
                    ts[cL * 132 + rL + hh * 8]       = v0;
                    ts[(cL + 1) * 132 + rL + hh * 8] = v1;
                }
            }
        __syncthreads();
        int bb = cRow >> 11;
        int s0 = cRow & (SEQ - 1);
        __half* dst = Ch + (size_t)bb * SEQ * DIM;
#pragma unroll
        for (int i = 0; i < 16; i++) {
            int cc = wid * 16 + i;
            __half2 p0 = __halves2half2(__float2half(ts[cc * 132 + lane * 4 + 0]),
                                        __float2half(ts[cc * 132 + lane * 4 + 1]));
            __half2 p1 = __halves2half2(__float2half(ts[cc * 132 + lane * 4 + 2]),
                                        __float2half(ts[cc * 132 + lane * 4 + 3]));
            __half* dp = dst + (size_t)(cCol + cc) * SEQ + s0 + lane * 4;
            *(__half2*)(dp)     = p0;
            *(__half2*)(dp + 2) = p1;
        }
        return;
    }

#pragma unroll
    for (int mi = 0; mi < 2; mi++) {
#pragma unroll
        for (int ni = 0; ni < 8; ni++) {
            int row0 = cRow + wm * 32 + mi * 16 + (lane >> 2);
            int col  = cCol + wn * 64 + ni * 8 + (lane & 3) * 2;
#pragma unroll
            for (int hh = 0; hh < 2; hh++) {
                int r = row0 + hh * 8;
                float v0 = acc[mi][ni][hh * 2];
                float v1 = acc[mi][ni][hh * 2 + 1];
                if (MODE == 1) { v0 *= QK_SCALE; v1 *= QK_SCALE; }
                if (bias) { v0 += bias[col]; v1 += bias[col + 1]; }
                if (OUTP == 0 && res) {
                    const float2 rr = *(const float2*)(res + (size_t)r * ldC + col);
                    v0 += rr.x; v1 += rr.y;
                }
                if (RELU) { v0 = fmaxf(v0, 0.f); v1 = fmaxf(v1, 0.f); }
                if (OUTP == 0) {
                    *(float2*)(Cf + (size_t)r * ldC + col) = make_float2(v0, v1);
                } else {
                    *(__half2*)(Ch + (size_t)r * ldC + col) =
                        __halves2half2(__float2half(v0), __float2half(v1));
                }
            }
        }
    }
}

// ------- batched weight transpose: 6 matrices in one launch -----------------
struct TPtrs { const float* src[6]; __half* dst[6]; };
__global__ void transpose_all(TPtrs p)
{
    const float* in = p.src[blockIdx.z];
    __half* out = p.dst[blockIdx.z];
    __shared__ float t[32][33];
    int x = blockIdx.x * 32 + threadIdx.x;
    int y = blockIdx.y * 32 + threadIdx.y;
#pragma unroll
    for (int j = 0; j < 32; j += 8)
        t[threadIdx.y + j][threadIdx.x] = in[(size_t)(y + j) * DIM + x];
    __syncthreads();
    x = blockIdx.y * 32 + threadIdx.x;
    y = blockIdx.x * 32 + threadIdx.y;
#pragma unroll
    for (int j = 0; j < 32; j += 8)
        out[(size_t)(y + j) * DIM + x] = __float2half(t[threadIdx.x][threadIdx.y + j]);
}

// ------- bias concat: o[0:D]=a, o[D:2D]=b -----------------------------------
__global__ void concat2(const float* __restrict__ a, const float* __restrict__ b,
                        float* __restrict__ o)
{
    int i = blockIdx.x * 256 + threadIdx.x;
    if (i < DIM) { o[i] = a[i]; o[i + DIM] = b[i]; }
}

// ------- LayerNorm: warp-per-row (MLP=8, no block barriers) -----------------
// ddof=1, eps on std. Block = 8 warps = 8 rows; grid = ROWS/8.
__global__ void __launch_bounds__(256)
ln_kernel(const float* __restrict__ x, const float* __restrict__ g,
          const float* __restrict__ be, __half* __restrict__ y)
{
    int row  = blockIdx.x * 8 + (threadIdx.x >> 5);
    int lane = threadIdx.x & 31;
    const float* xr = x + (size_t)row * DIM;

    float4 v[8];
    float s = 0.f;
#pragma unroll
    for (int i = 0; i < 8; i++) {                    // 8 independent LDG.128
        v[i] = *(const float4*)(xr + i * 128 + lane * 4);
        s += v[i].x + v[i].y + v[i].z + v[i].w;
    }
#pragma unroll
    for (int o = 16; o > 0; o >>= 1) s += __shfl_xor_sync(~0u, s, o);
    float mean = s * (1.0f / DIM);

    float q = 0.f;
#pragma unroll
    for (int i = 0; i < 8; i++) {
        v[i].x -= mean; v[i].y -= mean; v[i].z -= mean; v[i].w -= mean;
        q += v[i].x * v[i].x + v[i].y * v[i].y + v[i].z * v[i].z + v[i].w * v[i].w;
    }
#pragma unroll
    for (int o = 16; o > 0; o >>= 1) q += __shfl_xor_sync(~0u, q, o);
    float stdv = sqrtf(q / (float)(DIM - 1));
    float inv  = 1.0f / (stdv + 1e-6f);

    __half* yr = y + (size_t)row * DIM;
#pragma unroll
    for (int i = 0; i < 8; i++) {
        int c = i * 128 + lane * 4;
        float4 gg = *(const float4*)(g + c);
        float4 bb = *(const float4*)(be + c);
        __half2 o0 = __halves2half2(__float2half(gg.x * v[i].x * inv + bb.x),
                                    __float2half(gg.y * v[i].y * inv + bb.y));
        __half2 o1 = __halves2half2(__float2half(gg.z * v[i].z * inv + bb.z),
                                    __float2half(gg.w * v[i].w * inv + bb.w));
        *(__half2*)(yr + c)     = o0;
        *(__half2*)(yr + c + 2) = o1;
    }
}

// ------- causal softmax (fp16 scores in, fp16 probs out) --------------------
__global__ void softmax_kernel(const __half* __restrict__ scores,
                               __half* __restrict__ probs)
{
    int row = blockIdx.x;
    int b = row >> 11;
    int s = row & (SEQ - 1);
    size_t off = (size_t)b * SEQ * SEQ + (size_t)s * SEQ;
    const __half* p = scores + off;
    __half* o = probs + off;
    int cnt = s + 1;
    int blockEnd = ((s >> 7) + 1) << 7;        // next 128 boundary (AV K-limit)
    int t = threadIdx.x, lane = t & 31, wid = t >> 5;
    __shared__ float red[8];
    __shared__ float bc;

    float e[8];
    float mx = -INFINITY;
#pragma unroll
    for (int i = 0; i < 8; i++) {
        int j = t + i * 256;
        e[i] = (j < cnt) ? __half2float(p[j]) : -INFINITY;
        mx = fmaxf(mx, e[i]);
    }
#pragma unroll
    for (int oo = 16; oo > 0; oo >>= 1) mx = fmaxf(mx, __shfl_xor_sync(~0u, mx, oo));
    if (lane == 0) red[wid] = mx;
    __syncthreads();
    if (wid == 0) {
        float r = (lane < 8) ? red[lane] : -INFINITY;
#pragma unroll
        for (int oo = 4; oo > 0; oo >>= 1) r = fmaxf(r, __shfl_xor_sync(~0u, r, oo));
        if (lane == 0) bc = r;
    }
    __syncthreads();
    mx = bc;

    float sum = 0.f;
#pragma unroll
    for (int i = 0; i < 8; i++) {
        int j = t + i * 256;
        if (j < cnt) { e[i] = __expf(e[i] - mx); sum += e[i]; }
    }
#pragma unroll
    for (int oo = 16; oo > 0; oo >>= 1) sum += __shfl_xor_sync(~0u, sum, oo);
    __syncthreads();
    if (lane == 0) red[wid] = sum;
    __syncthreads();
    if (wid == 0) {
        float r = (lane < 8) ? red[lane] : 0.f;
#pragma unroll
        for (int oo = 4; oo > 0; oo >>= 1) r += __shfl_xor_sync(~0u, r, oo);
        if (lane == 0) bc = r;
    }
    __syncthreads();
    float inv = 1.0f / bc;

#pragma unroll
    for (int i = 0; i < 8; i++) {
        int j = t + i * 256;
        if (j < cnt) o[j] = __float2half(e[i] * inv);
    }
    for (int j = cnt + t; j < blockEnd; j += 256) o[j] = __float2half(0.f);
}

// ---------------- launch -----------------------------------------------------
extern "C" void kernel_launch(void* const* d_in, const int* in_sizes, int n_in,
                              void* d_out, int out_size)
{
    const float* x   = (const float*)d_in[0];
    const float* wq  = (const float*)d_in[1];
    const float* bq  = (const float*)d_in[2];
    const float* wk  = (const float*)d_in[3];
    const float* bk  = (const float*)d_in[4];
    const float* wv  = (const float*)d_in[5];
    const float* bv  = (const float*)d_in[6];
    const float* wo  = (const float*)d_in[7];
    const float* bo  = (const float*)d_in[8];
    const float* w1  = (const float*)d_in[9];
    const float* b1  = (const float*)d_in[10];
    const float* w2  = (const float*)d_in[11];
    const float* b2  = (const float*)d_in[12];
    const float* g1  = (const float*)d_in[13];
    const float* be1 = (const float*)d_in[14];
    const float* g2  = (const float*)d_in[15];
    const float* be2 = (const float*)d_in[16];
    float* out = (float*)d_out;

    __half *ln1, *qk, *vt, *ctx, *ln2, *m1, *sc, *sp, *wt;
    float *h, *bqk;
    cudaGetSymbolAddress((void**)&ln1, g_ln1);
    cudaGetSymbolAddress((void**)&qk,  g_qk);
    cudaGetSymbolAddress((void**)&vt,  g_vt);
    cudaGetSymbolAddress((void**)&ctx, g_ctx);
    cudaGetSymbolAddress((void**)&h,   g_h);
    cudaGetSymbolAddress((void**)&ln2, g_ln2);
    cudaGetSymbolAddress((void**)&m1,  g_m1);
    cudaGetSymbolAddress((void**)&sc,  g_sc);
    cudaGetSymbolAddress((void**)&sp,  g_sp);
    cudaGetSymbolAddress((void**)&wt,  g_wt);
    cudaGetSymbolAddress((void**)&bqk, g_bqk);

    __half* wqt = wt + 0 * DIM * DIM;     // Q|K contiguous for fused proj
    __half* wvt = wt + 2 * DIM * DIM;
    __half* wot = wt + 3 * DIM * DIM;
    __half* w1t = wt + 4 * DIM * DIM;
    __half* w2t = wt + 5 * DIM * DIM;

    cudaFuncSetAttribute(fp16_gemm<0, false, 0>, cudaFuncAttributeMaxDynamicSharedMemorySize, SMEMSZ);
    cudaFuncSetAttribute(fp16_gemm<0, false, 1>, cudaFuncAttributeMaxDynamicSharedMemorySize, SMEMSZ);
    cudaFuncSetAttribute(fp16_gemm<0, false, 2>, cudaFuncAttributeMaxDynamicSharedMemorySize, SMEMSZ);
    cudaFuncSetAttribute(fp16_gemm<0, true,  1>, cudaFuncAttributeMaxDynamicSharedMemorySize, SMEMSZ);
    cudaFuncSetAttribute(fp16_gemm<1, false, 1>, cudaFuncAttributeMaxDynamicSharedMemorySize, SMEMSZ);
    cudaFuncSetAttribute(fp16_gemm<2, false, 1>, cudaFuncAttributeMaxDynamicSharedMemorySize, SMEMSZ);

    dim3 blk(256);
    dim3 gQKP(2 * DIM / BN, ROWS / BM, 1);  // fused Q|K proj: (16, 64)
    dim3 gD(DIM / BN, ROWS / BM, 1);        // dense: (8, 64)
    dim3 gQK(SEQ / BN, SEQ / BM, BATCH);    // scores: (16,16,4)
    dim3 gAV(DIM / BN, SEQ / BM, BATCH);    // (8,16,4)
    dim3 tblk(32, 8);
    dim3 tAll(DIM / 32, DIM / 32, 6);

    // LN1 -> fp16 (warp-per-row)
    ln_kernel<<<ROWS / 8, 256>>>(x, g1, be1, ln1);
    // all weight transposes in ONE launch ([K,N] -> [N,K] fp16)
    TPtrs tp;
    tp.src[0] = wq; tp.dst[0] = wqt;
    tp.src[1] = wk; tp.dst[1] = wqt + DIM * DIM;
    tp.src[2] = wv; tp.dst[2] = wvt;
    tp.src[3] = wo; tp.dst[3] = wot;
    tp.src[4] = w1; tp.dst[4] = w1t;
    tp.src[5] = w2; tp.dst[5] = w2t;
    transpose_all<<<tAll, tblk>>>(tp);
    concat2<<<4, 256>>>(bq, bk, bqk);
    // fused Q|K projection -> qk fp16 [ROWS, 2048]
    fp16_gemm<0, false, 1><<<gQKP, blk, SMEMSZ>>>(ln1, wqt, bqk, nullptr, qk,
        DIM, DIM, DIM, 2 * DIM, 0, 0, 0);
    // V projection -> fp16 V^T directly
    fp16_gemm<0, false, 2><<<gD, blk, SMEMSZ>>>(ln1, wvt, bv, nullptr, vt,
        DIM, DIM, DIM, DIM, 0, 0, 0);
    // scores = Q K^T / sqrt(S) -> fp16 (causal block skip)
    fp16_gemm<1, false, 1><<<gQK, blk, SMEMSZ>>>(qk, qk + DIM, nullptr, nullptr, sc,
        DIM, 2 * DIM, 2 * DIM, SEQ,
        (size_t)SEQ * 2 * DIM, (size_t)SEQ * 2 * DIM, (size_t)SEQ * SEQ);
    // softmax (fp16 in) -> fp16 probs
    softmax_kernel<<<ROWS, 256>>>(sc, sp);
    // ctx = P V -> fp16 (causal K-limit, heavy-first)
    fp16_gemm<2, false, 1><<<gAV, blk, SMEMSZ>>>(sp, vt, nullptr, nullptr, ctx,
        SEQ, SEQ, SEQ, DIM,
        (size_t)SEQ * SEQ, (size_t)SEQ * DIM, (size_t)SEQ * DIM);
    // h = ctx@wo + bo + x -> fp32
    fp16_gemm<0, false, 0><<<gD, blk, SMEMSZ>>>(ctx, wot, bo, x, h,
        DIM, DIM, DIM, DIM, 0, 0, 0);
    // LN2 -> fp16 (warp-per-row)
    ln_kernel<<<ROWS / 8, 256>>>(h, g2, be2, ln2);
    // mlp1 = relu(ln2@w1 + b1) -> fp16
    fp16_gemm<0, true, 1><<<gD, blk, SMEMSZ>>>(ln2, w1t, b1, nullptr, m1,
        DIM, DIM, DIM, DIM, 0, 0, 0);
    // out = mlp1@w2 + b2 + h -> fp32
    fp16_gemm<0, false, 0><<<gD, blk, SMEMSZ>>>(m1, w2t, b2, h, out,
        DIM, DIM, DIM, DIM, 0, 0, 0);
}

// round 17
// speedup vs baseline: 1.0036x; 1.0036x over previous
#include <cuda_runtime.h>
#include <cuda_fp16.h>
#include <stdint.h>
#include <math.h>

// Problem shape (fixed): B=4, S=2048, D=1024
#define BATCH 4
#define SEQ   2048
#define DIM   1024
#define ROWS  (BATCH*SEQ)          // 8192
#define QK_SCALE 0.0220970869f     // 1/sqrt(2048)

// fp16 GEMM tiling (R13 core): CTA 128x128, BK=64; 8 warps (4x2) -> 32x64
#define BM 128
#define BN 128
#define BK 64
#define STG 32768                  // A 16K | B 16K (fp16)
#define SMEMSZ (3*STG)             // 96KB, 3-stage ring

// ---------------- scratch (device globals; no allocation allowed) -----------
__device__ __half g_ln1 [ROWS*DIM];
__device__ __half g_qk  [ROWS*2*DIM];             // fused Q|K [ROWS, 2048]
__device__ __half g_vt  [ROWS*DIM];               // V^T per batch [D, S]
__device__ __half g_ctx [ROWS*DIM];
__device__ float  g_h   [ROWS*DIM];
__device__ __half g_ln2 [ROWS*DIM];
__device__ __half g_m1  [ROWS*DIM];
__device__ __half g_sc  [(size_t)BATCH*SEQ*SEQ];  // raw scores fp16 (32MB)
__device__ __half g_sp  [(size_t)BATCH*SEQ*SEQ];  // fp16 probs (32MB)
__device__ __half g_wt  [6*DIM*DIM];              // transposed weights fp16
__device__ float  g_bqk [2*DIM];                  // concat bias bq|bk

// ======================= helpers =============================================
__device__ __forceinline__ uint32_t smem_u32(const void* p) {
    uint32_t a;
    asm("{ .reg .u64 t; cvta.to.shared.u64 t, %1; cvt.u32.u64 %0, t; }"
        : "=r"(a) : "l"(p));
    return a;
}
__device__ __forceinline__ void cp16(uint32_t dst, const void* src) {
    asm volatile("cp.async.cg.shared.global [%0], [%1], 16;"
                 :: "r"(dst), "l"(src) : "memory");
}
__device__ __forceinline__ uint32_t sw128o(uint32_t o) {
    return o ^ ((o >> 3) & 0x70);
}
__device__ __forceinline__ void ldsm_x4(uint32_t* r, uint32_t addr) {
    asm volatile("ldmatrix.sync.aligned.m8n8.x4.shared.b16 {%0,%1,%2,%3}, [%4];"
                 : "=r"(r[0]), "=r"(r[1]), "=r"(r[2]), "=r"(r[3]) : "r"(addr));
}
__device__ __forceinline__ void mma_fp16(float* c, const uint32_t* a,
                                         uint32_t b0, uint32_t b1) {
    asm volatile("mma.sync.aligned.m16n8k16.row.col.f32.f16.f16.f32 "
                 "{%0,%1,%2,%3}, {%4,%5,%6,%7}, {%8,%9}, {%0,%1,%2,%3};"
                 : "+f"(c[0]), "+f"(c[1]), "+f"(c[2]), "+f"(c[3])
                 : "r"(a[0]), "r"(a[1]), "r"(a[2]), "r"(a[3]), "r"(b0), "r"(b1));
}

// ============ fp16 HMMA GEMM: C[M,N] = A[M,K] @ B[N,K]^T =====================
// fp32 accumulate; bias/res/relu on fp32 accumulators.
// MODE: 0=dense, 1=QK (scale, causal block-skip), 2=AV (causal K-limit,
//       heavy-tiles-first)
// OUTP: 0 -> fp32 C (+res), 1 -> fp16 C, 2 -> fp16 transposed V^T
template<int MODE, bool RELU, int OUTP>
__global__ void __launch_bounds__(256, 2)
fp16_gemm(const __half* __restrict__ A, const __half* __restrict__ B,
          const float* __restrict__ bias, const float* __restrict__ res,
          void* __restrict__ Cv, int K, int ldA, int ldB, int ldC,
          size_t sA, size_t sB, size_t sC)
{
    int by = (MODE == 2) ? (gridDim.y - 1 - blockIdx.y) : blockIdx.y;
    int cRow = by * BM;
    int cCol = blockIdx.x * BN;
    if (MODE == 1 && cCol > cRow + BM - 1) return;   // fully above diagonal

    A += blockIdx.z * sA;
    B += blockIdx.z * sB;
    float*  Cf = (float*)Cv + (OUTP == 0 ? blockIdx.z * sC : 0);
    __half* Ch = (__half*)Cv + (OUTP == 1 ? blockIdx.z * sC : 0);
    if (OUTP == 0 && res) res += blockIdx.z * sC;

    int nc = (MODE == 2) ? (cRow + BM) / BK : K / BK;

    extern __shared__ __align__(1024) char smem[];
    uint32_t base = smem_u32(smem);
    int tid = threadIdx.x, lane = tid & 31, wid = tid >> 5;
    int wm = wid >> 1, wn = wid & 1;      // 4x2 warp grid, warp tile 32x64

    auto stage = [&](int c) {
        int kt = c * BK;
        uint32_t sb = base + (c % 3) * STG;
#pragma unroll
        for (int i = 0; i < 4; i++) {                 // A: 1024 granules of 16B
            int g = tid + i * 256;
            int row = g >> 3, ch = g & 7;
            cp16(sb + sw128o((uint32_t)(row * 128 + ch * 16)),
                 A + (size_t)(cRow + row) * ldA + kt + ch * 8);
        }
#pragma unroll
        for (int i = 0; i < 4; i++) {                 // B: 1024 granules
            int g = tid + i * 256;
            int row = g >> 3, ch = g & 7;
            cp16(sb + 16384 + sw128o((uint32_t)(row * 128 + ch * 16)),
                 B + (size_t)(cCol + row) * ldB + kt + ch * 8);
        }
        asm volatile("cp.async.commit_group;" ::: "memory");
    };

    float acc[2][8][4];
#pragma unroll
    for (int mi = 0; mi < 2; mi++)
#pragma unroll
        for (int ni = 0; ni < 8; ni++)
#pragma unroll
            for (int j = 0; j < 4; j++) acc[mi][ni][j] = 0.f;

    // fp16 m16n8k16 fragment offsets (validated mapping, non-trans B)
    int a_r  = lane & 15;
    int a_kb = (lane >> 4) << 4;
    int b_n  = (lane & 7) + ((lane >> 4) << 3);
    int b_kb = ((lane >> 3) & 1) << 4;

    stage(0);
    if (nc > 1) stage(1);
    for (int c = 0; c < nc; c++) {
        if (c + 1 < nc) {
            asm volatile("cp.async.wait_group 1;" ::: "memory");
        } else {
            asm volatile("cp.async.wait_group 0;" ::: "memory");
        }
        __syncthreads();
        // stage slot (c+2)%3 == (c-1)%3: its only reader (compute c-1) is
        // done by the barrier above — no trailing sync needed.
        if (c + 2 < nc) stage(c + 2);

        uint32_t sb = base + (c % 3) * STG;
        uint32_t aB = sb, bB = sb + 16384;

        // ---- software-pipelined fragment loads (1-step lookahead) ----
        uint32_t afr[2][2][4];   // a ping-pong per ks
        uint32_t bfr[2][4];      // b ping-pong per (ks,pp) step
#pragma unroll
        for (int mi = 0; mi < 2; mi++) {
            int r = wm * 32 + mi * 16 + a_r;
            ldsm_x4(afr[0][mi], aB + sw128o((uint32_t)(r * 128 + a_kb)));
        }
        {
            int n = wn * 64 + b_n;
            ldsm_x4(bfr[0], bB + sw128o((uint32_t)(n * 128 + b_kb)));
        }
#pragma unroll
        for (int it = 0; it < 16; it++) {
            int ks = it >> 2, pp = it & 3;
            int cb = it & 1;
            if (it + 1 < 16) {                     // prefetch next b
                int itn = it + 1;
                int ksn = itn >> 2, ppn = itn & 3;
                int n = wn * 64 + ppn * 16 + b_n;
                ldsm_x4(bfr[cb ^ 1],
                        bB + sw128o((uint32_t)(n * 128 + ksn * 32 + b_kb)));
            }
            if (pp == 0 && ks + 1 < 4) {           // prefetch next a (early)
#pragma unroll
                for (int mi = 0; mi < 2; mi++) {
                    int r = wm * 32 + mi * 16 + a_r;
                    ldsm_x4(afr[(ks + 1) & 1][mi],
                            aB + sw128o((uint32_t)(r * 128 + (ks + 1) * 32 + a_kb)));
                }
            }
#pragma unroll
            for (int mi = 0; mi < 2; mi++) {
                mma_fp16(acc[mi][pp * 2],     afr[ks & 1][mi], bfr[cb][0], bfr[cb][1]);
                mma_fp16(acc[mi][pp * 2 + 1], afr[ks & 1][mi], bfr[cb][2], bfr[cb][3]);
            }
        }
    }

    // ---- epilogue ----
    if (OUTP == 2) {
        __syncthreads();   // all warps done with mainloop smem before reuse
        // transposed fp16 store: acc -> smem [col][row] -> coalesced V^T write
        float* ts = (float*)smem;                     // 128 x 132 floats (67.6KB)
#pragma unroll
        for (int mi = 0; mi < 2; mi++)
#pragma unroll
            for (int ni = 0; ni < 8; ni++) {
                int rL = wm * 32 + mi * 16 + (lane >> 2);
                int cL = wn * 64 + ni * 8 + (lane & 3) * 2;
#pragma unroll
                for (int hh = 0; hh < 2; hh++) {
                    float v0 = acc[mi][ni][hh * 2];
                    float v1 = acc[mi][ni][hh * 2 + 1];
                    if (bias) { v0 += bias[cCol + cL]; v1 += bias[cCol + cL + 1]; }
                    ts[cL * 132 + rL + hh * 8]       = v0;
                    ts[(cL + 1) * 132 + rL + hh * 8] = v1;
                }
            }
        __syncthreads();
        int bb = cRow >> 11;
        int s0 = cRow & (SEQ - 1);
        __half* dst = Ch + (size_t)bb * SEQ * DIM;
#pragma unroll
        for (int i = 0; i < 16; i++) {
            int cc = wid * 16 + i;
            __half2 p0 = __halves2half2(__float2half(ts[cc * 132 + lane * 4 + 0]),
                                        __float2half(ts[cc * 132 + lane * 4 + 1]));
            __half2 p1 = __halves2half2(__float2half(ts[cc * 132 + lane * 4 + 2]),
                                        __float2half(ts[cc * 132 + lane * 4 + 3]));
            __half* dp = dst + (size_t)(cCol + cc) * SEQ + s0 + lane * 4;
            *(__half2*)(dp)     = p0;
            *(__half2*)(dp + 2) = p1;
        }
        return;
    }

#pragma unroll
    for (int mi = 0; mi < 2; mi++) {
#pragma unroll
        for (int ni = 0; ni < 8; ni++) {
            int row0 = cRow + wm * 32 + mi * 16 + (lane >> 2);
            int col  = cCol + wn * 64 + ni * 8 + (lane & 3) * 2;
#pragma unroll
            for (int hh = 0; hh < 2; hh++) {
                int r = row0 + hh * 8;
                float v0 = acc[mi][ni][hh * 2];
                float v1 = acc[mi][ni][hh * 2 + 1];
                if (MODE == 1) { v0 *= QK_SCALE; v1 *= QK_SCALE; }
                if (bias) { v0 += bias[col]; v1 += bias[col + 1]; }
                if (OUTP == 0 && res) {
                    const float2 rr = *(const float2*)(res + (size_t)r * ldC + col);
                    v0 += rr.x; v1 += rr.y;
                }
                if (RELU) { v0 = fmaxf(v0, 0.f); v1 = fmaxf(v1, 0.f); }
                if (OUTP == 0) {
                    *(float2*)(Cf + (size_t)r * ldC + col) = make_float2(v0, v1);
                } else {
                    *(__half2*)(Ch + (size_t)r * ldC + col) =
                        __halves2half2(__float2half(v0), __float2half(v1));
                }
            }
        }
    }
}

// ------- batched weight transpose: 6 matrices in one launch -----------------
struct TPtrs { const float* src[6]; __half* dst[6]; };
__global__ void transpose_all(TPtrs p)
{
    const float* in = p.src[blockIdx.z];
    __half* out = p.dst[blockIdx.z];
    __shared__ float t[32][33];
    int x = blockIdx.x * 32 + threadIdx.x;
    int y = blockIdx.y * 32 + threadIdx.y;
#pragma unroll
    for (int j = 0; j < 32; j += 8)
        t[threadIdx.y + j][threadIdx.x] = in[(size_t)(y + j) * DIM + x];
    __syncthreads();
    x = blockIdx.y * 32 + threadIdx.x;
    y = blockIdx.x * 32 + threadIdx.y;
#pragma unroll
    for (int j = 0; j < 32; j += 8)
        out[(size_t)(y + j) * DIM + x] = __float2half(t[threadIdx.x][threadIdx.y + j]);
}

// ------- bias concat: o[0:D]=a, o[D:2D]=b -----------------------------------
__global__ void concat2(const float* __restrict__ a, const float* __restrict__ b,
                        float* __restrict__ o)
{
    int i = blockIdx.x * 256 + threadIdx.x;
    if (i < DIM) { o[i] = a[i]; o[i + DIM] = b[i]; }
}

// ------- LayerNorm: warp-per-row (MLP=8, no block barriers) -----------------
// ddof=1, eps on std. Block = 8 warps = 8 rows; grid = ROWS/8.
__global__ void __launch_bounds__(256)
ln_kernel(const float* __restrict__ x, const float* __restrict__ g,
          const float* __restrict__ be, __half* __restrict__ y)
{
    int row  = blockIdx.x * 8 + (threadIdx.x >> 5);
    int lane = threadIdx.x & 31;
    const float* xr = x + (size_t)row * DIM;

    float4 v[8];
    float s = 0.f;
#pragma unroll
    for (int i = 0; i < 8; i++) {                    // 8 independent LDG.128
        v[i] = *(const float4*)(xr + i * 128 + lane * 4);
        s += v[i].x + v[i].y + v[i].z + v[i].w;
    }
#pragma unroll
    for (int o = 16; o > 0; o >>= 1) s += __shfl_xor_sync(~0u, s, o);
    float mean = s * (1.0f / DIM);

    float q = 0.f;
#pragma unroll
    for (int i = 0; i < 8; i++) {
        v[i].x -= mean; v[i].y -= mean; v[i].z -= mean; v[i].w -= mean;
        q += v[i].x * v[i].x + v[i].y * v[i].y + v[i].z * v[i].z + v[i].w * v[i].w;
    }
#pragma unroll
    for (int o = 16; o > 0; o >>= 1) q += __shfl_xor_sync(~0u, q, o);
    float stdv = sqrtf(q / (float)(DIM - 1));
    float inv  = 1.0f / (stdv + 1e-6f);

    __half* yr = y + (size_t)row * DIM;
#pragma unroll
    for (int i = 0; i < 8; i++) {
        int c = i * 128 + lane * 4;
        float4 gg = *(const float4*)(g + c);
        float4 bb = *(const float4*)(be + c);
        __half2 o0 = __halves2half2(__float2half(gg.x * v[i].x * inv + bb.x),
                                    __float2half(gg.y * v[i].y * inv + bb.y));
        __half2 o1 = __halves2half2(__float2half(gg.z * v[i].z * inv + bb.z),
                                    __float2half(gg.w * v[i].w * inv + bb.w));
        *(__half2*)(yr + c)     = o0;
        *(__half2*)(yr + c + 2) = o1;
    }
}

// ------- causal softmax (fp16 scores in, fp16 probs out) --------------------
__global__ void softmax_kernel(const __half* __restrict__ scores,
                               __half* __restrict__ probs)
{
    int row = blockIdx.x;
    int b = row >> 11;
    int s = row & (SEQ - 1);
    size_t off = (size_t)b * SEQ * SEQ + (size_t)s * SEQ;
    const __half* p = scores + off;
    __half* o = probs + off;
    int cnt = s + 1;
    int blockEnd = ((s >> 7) + 1) << 7;        // next 128 boundary (AV K-limit)
    int t = threadIdx.x, lane = t & 31, wid = t >> 5;
    __shared__ float red[8];
    __shared__ float bc;

    float e[8];
    float mx = -INFINITY;
#pragma unroll
    for (int i = 0; i < 8; i++) {
        int j = t + i * 256;
        e[i] = (j < cnt) ? __half2float(p[j]) : -INFINITY;
        mx = fmaxf(mx, e[i]);
    }
#pragma unroll
    for (int oo = 16; oo > 0; oo >>= 1) mx = fmaxf(mx, __shfl_xor_sync(~0u, mx, oo));
    if (lane == 0) red[wid] = mx;
    __syncthreads();
    if (wid == 0) {
        float r = (lane < 8) ? red[lane] : -INFINITY;
#pragma unroll
        for (int oo = 4; oo > 0; oo >>= 1) r = fmaxf(r, __shfl_xor_sync(~0u, r, oo));
        if (lane == 0) bc = r;
    }
    __syncthreads();
    mx = bc;

    float sum = 0.f;
#pragma unroll
    for (int i = 0; i < 8; i++) {
        int j = t + i * 256;
        if (j < cnt) { e[i] = __expf(e[i] - mx); sum += e[i]; }
    }
#pragma unroll
    for (int oo = 16; oo > 0; oo >>= 1) sum += __shfl_xor_sync(~0u, sum, oo);
    __syncthreads();
    if (lane == 0) red[wid] = sum;
    __syncthreads();
    if (wid == 0) {
        float r = (lane < 8) ? red[lane] : 0.f;
#pragma unroll
        for (int oo = 4; oo > 0; oo >>= 1) r += __shfl_xor_sync(~0u, r, oo);
        if (lane == 0) bc = r;
    }
    __syncthreads();
    float inv = 1.0f / bc;

#pragma unroll
    for (int i = 0; i < 8; i++) {
        int j = t + i * 256;
        if (j < cnt) o[j] = __float2half(e[i] * inv);
    }
    for (int j = cnt + t; j < blockEnd; j += 256) o[j] = __float2half(0.f);
}

// ---------------- launch -----------------------------------------------------
extern "C" void kernel_launch(void* const* d_in, const int* in_sizes, int n_in,
                              void* d_out, int out_size)
{
    const float* x   = (const float*)d_in[0];
    const float* wq  = (const float*)d_in[1];
    const float* bq  = (const float*)d_in[2];
    const float* wk  = (const float*)d_in[3];
    const float* bk  = (const float*)d_in[4];
    const float* wv  = (const float*)d_in[5];
    const float* bv  = (const float*)d_in[6];
    const float* wo  = (const float*)d_in[7];
    const float* bo  = (const float*)d_in[8];
    const float* w1  = (const float*)d_in[9];
    const float* b1  = (const float*)d_in[10];
    const float* w2  = (const float*)d_in[11];
    const float* b2  = (const float*)d_in[12];
    const float* g1  = (const float*)d_in[13];
    const float* be1 = (const float*)d_in[14];
    const float* g2  = (const float*)d_in[15];
    const float* be2 = (const float*)d_in[16];
    float* out = (float*)d_out;

    __half *ln1, *qk, *vt, *ctx, *ln2, *m1, *sc, *sp, *wt;
    float *h, *bqk;
    cudaGetSymbolAddress((void**)&ln1, g_ln1);
    cudaGetSymbolAddress((void**)&qk,  g_qk);
    cudaGetSymbolAddress((void**)&vt,  g_vt);
    cudaGetSymbolAddress((void**)&ctx, g_ctx);
    cudaGetSymbolAddress((void**)&h,   g_h);
    cudaGetSymbolAddress((void**)&ln2, g_ln2);
    cudaGetSymbolAddress((void**)&m1,  g_m1);
    cudaGetSymbolAddress((void**)&sc,  g_sc);
    cudaGetSymbolAddress((void**)&sp,  g_sp);
    cudaGetSymbolAddress((void**)&wt,  g_wt);
    cudaGetSymbolAddress((void**)&bqk, g_bqk);

    __half* wqt = wt + 0 * DIM * DIM;     // Q|K contiguous for fused proj
    __half* wvt = wt + 2 * DIM * DIM;
    __half* wot = wt + 3 * DIM * DIM;
    __half* w1t = wt + 4 * DIM * DIM;
    __half* w2t = wt + 5 * DIM * DIM;

    cudaFuncSetAttribute(fp16_gemm<0, false, 0>, cudaFuncAttributeMaxDynamicSharedMemorySize, SMEMSZ);
    cudaFuncSetAttribute(fp16_gemm<0, false, 1>, cudaFuncAttributeMaxDynamicSharedMemorySize, SMEMSZ);
    cudaFuncSetAttribute(fp16_gemm<0, false, 2>, cudaFuncAttributeMaxDynamicSharedMemorySize, SMEMSZ);
    cudaFuncSetAttribute(fp16_gemm<0, true,  1>, cudaFuncAttributeMaxDynamicSharedMemorySize, SMEMSZ);
    cudaFuncSetAttribute(fp16_gemm<1, false, 1>, cudaFuncAttributeMaxDynamicSharedMemorySize, SMEMSZ);
    cudaFuncSetAttribute(fp16_gemm<2, false, 1>, cudaFuncAttributeMaxDynamicSharedMemorySize, SMEMSZ);

    dim3 blk(256);
    dim3 gQKP(2 * DIM / BN, ROWS / BM, 1);  // fused Q|K proj: (16, 64)
    dim3 gD(DIM / BN, ROWS / BM, 1);        // dense: (8, 64)
    dim3 gQK(SEQ / BN, SEQ / BM, BATCH);    // scores: (16,16,4)
    dim3 gAV(DIM / BN, SEQ / BM, BATCH);    // (8,16,4)
    dim3 tblk(32, 8);
    dim3 tAll(DIM / 32, DIM / 32, 6);

    // LN1 -> fp16 (warp-per-row)
    ln_kernel<<<ROWS / 8, 256>>>(x, g1, be1, ln1);
    // all weight transposes in ONE launch ([K,N] -> [N,K] fp16)
    TPtrs tp;
    tp.src[0] = wq; tp.dst[0] = wqt;
    tp.src[1] = wk; tp.dst[1] = wqt + DIM * DIM;
    tp.src[2] = wv; tp.dst[2] = wvt;
    tp.src[3] = wo; tp.dst[3] = wot;
    tp.src[4] = w1; tp.dst[4] = w1t;
    tp.src[5] = w2; tp.dst[5] = w2t;
    transpose_all<<<tAll, tblk>>>(tp);
    concat2<<<4, 256>>>(bq, bk, bqk);
    // fused Q|K projection -> qk fp16 [ROWS, 2048]
    fp16_gemm<0, false, 1><<<gQKP, blk, SMEMSZ>>>(ln1, wqt, bqk, nullptr, qk,
        DIM, DIM, DIM, 2 * DIM, 0, 0, 0);
    // V projection -> fp16 V^T directly
    fp16_gemm<0, false, 2><<<gD, blk, SMEMSZ>>>(ln1, wvt, bv, nullptr, vt,
        DIM, DIM, DIM, DIM, 0, 0, 0);
    // scores = Q K^T / sqrt(S) -> fp16 (causal block skip)
    fp16_gemm<1, false, 1><<<gQK, blk, SMEMSZ>>>(qk, qk + DIM, nullptr, nullptr, sc,
        DIM, 2 * DIM, 2 * DIM, SEQ,
        (size_t)SEQ * 2 * DIM, (size_t)SEQ * 2 * DIM, (size_t)SEQ * SEQ);
    // softmax (fp16 in) -> fp16 probs
    softmax_kernel<<<ROWS, 256>>>(sc, sp);
    // ctx = P V -> fp16 (causal K-limit, heavy-first)
    fp16_gemm<2, false, 1><<<gAV, blk, SMEMSZ>>>(sp, vt, nullptr, nullptr, ctx,
        SEQ, SEQ, SEQ, DIM,
        (size_t)SEQ * SEQ, (size_t)SEQ * DIM, (size_t)SEQ * DIM);
    // h = ctx@wo + bo + x -> fp32
    fp16_gemm<0, false, 0><<<gD, blk, SMEMSZ>>>(ctx, wot, bo, x, h,
        DIM, DIM, DIM, DIM, 0, 0, 0);
    // LN2 -> fp16 (warp-per-row)
    ln_kernel<<<ROWS / 8, 256>>>(h, g2, be2, ln2);
    // mlp1 = relu(ln2@w1 + b1) -> fp16
    fp16_gemm<0, true, 1><<<gD, blk, SMEMSZ>>>(ln2, w1t, b1, nullptr, m1,
        DIM, DIM, DIM, DIM, 0, 0, 0);
    // out = mlp1@w2 + b2 + h -> fp32
    fp16_gemm<0, false, 0><<<gD, blk, SMEMSZ>>>(m1, w2t, b2, h, out,
        DIM, DIM, DIM, DIM, 0, 0, 0);
}